// round 4
// baseline (speedup 1.0000x reference)
#include <cuda_runtime.h>

// TropicalDense: out[b,o] = max_{s,d} ( (s?-X[b,d]:X[b,d]) + K[s,d,o] )
// B=1024, D=512, O=256, float32.

#define B_DIM 1024
#define D_DIM 512
#define O_DIM 256

#define BM 32      // batch rows per block
#define BO 32      // output cols per block
#define DC 64      // d-chunk through shared
#define NTHREADS 128
#define PSTRIDE 34 // padded row stride in float2 (272B: 16B-aligned, conflict-friendly)

// packed f32x2 add on the fma pipe: one instr for (x+k0, -x+k1)
__device__ __forceinline__ void addx2(unsigned long long a, unsigned long long b,
                                      float& lo, float& hi) {
    unsigned long long d;
    asm("add.rn.f32x2 %0, %1, %2;" : "=l"(d) : "l"(a), "l"(b));
    asm("mov.b64 {%0, %1}, %2;" : "=f"(lo), "=f"(hi) : "l"(d));
}

__global__ void __launch_bounds__(NTHREADS, 4)
tropical_dense_kernel(const float* __restrict__ X,
                      const float* __restrict__ K,
                      float* __restrict__ out) {
    // Xp[dd][row] = (x, -x); Kp[dd][o] = (K0[d][o], K1[d][o])
    __shared__ float2 Xp[DC][PSTRIDE];
    __shared__ float2 Kp[DC][PSTRIDE];

    const int tid = threadIdx.x;
    const int to  = tid & 7;      // 0..7  : o-group (4 cols each)
    const int tb  = tid >> 3;     // 0..15 : batch group (2 rows each)
    const int b0  = blockIdx.y * BM;
    const int o0  = blockIdx.x * BO;

    float acc[2][4];
    #pragma unroll
    for (int i = 0; i < 2; i++)
        #pragma unroll
        for (int j = 0; j < 4; j++)
            acc[i][j] = __int_as_float(0xff800000);   // -inf

    for (int dc = 0; dc < D_DIM; dc += DC) {
        // ---- X tile loader: thread t -> row=t&31, d-float4 = t>>5 (+4k).
        // gmem reads are strided (row-major X, fixed d) but X traffic is tiny;
        // smem stores land conflict-free (consecutive rows in one dd-row).
        #pragma unroll
        for (int k = 0; k < 4; k++) {
            int row  = tid & 31;
            int col4 = (tid >> 5) + k * 4;          // 0..15
            float4 v = *reinterpret_cast<const float4*>(
                &X[(size_t)(b0 + row) * D_DIM + dc + col4 * 4]);
            Xp[col4 * 4 + 0][row] = make_float2(v.x, -v.x);
            Xp[col4 * 4 + 1][row] = make_float2(v.y, -v.y);
            Xp[col4 * 4 + 2][row] = make_float2(v.z, -v.z);
            Xp[col4 * 4 + 3][row] = make_float2(v.w, -v.w);
        }
        // ---- K tile loader: interleave (K0,K1) pairs, gmem float4-coalesced ----
        #pragma unroll
        for (int k = 0; k < 4; k++) {
            int o4 = tid & 7;                        // float4 index along o
            int dd = (tid >> 3) + k * 16;            // 0..63
            const float* p0 = &K[(size_t)(dc + dd) * O_DIM + o0 + o4 * 4];
            float4 a = *reinterpret_cast<const float4*>(p0);
            float4 b = *reinterpret_cast<const float4*>(p0 + (size_t)D_DIM * O_DIM);
            Kp[dd][o4 * 4 + 0] = make_float2(a.x, b.x);
            Kp[dd][o4 * 4 + 1] = make_float2(a.y, b.y);
            Kp[dd][o4 * 4 + 2] = make_float2(a.z, b.z);
            Kp[dd][o4 * 4 + 3] = make_float2(a.w, b.w);
        }
        __syncthreads();

        // ---- pipelined hot loop: per dd = 3 LDS.128 + 8 ADDX2 + 8 fmax-trees ----
        ulonglong2 xv = *reinterpret_cast<const ulonglong2*>(&Xp[0][tb * 2]);
        ulonglong2 ka = *reinterpret_cast<const ulonglong2*>(&Kp[0][to * 4]);
        ulonglong2 kb = *reinterpret_cast<const ulonglong2*>(&Kp[0][to * 4 + 2]);

        #pragma unroll 8
        for (int dd = 0; dd < DC; dd++) {
            ulonglong2 xc = xv, kac = ka, kbc = kb;
            if (dd + 1 < DC) {   // prefetch next iteration's operands first
                xv = *reinterpret_cast<const ulonglong2*>(&Xp[dd + 1][tb * 2]);
                ka = *reinterpret_cast<const ulonglong2*>(&Kp[dd + 1][to * 4]);
                kb = *reinterpret_cast<const ulonglong2*>(&Kp[dd + 1][to * 4 + 2]);
            }
            unsigned long long kp[4] = {kac.x, kac.y, kbc.x, kbc.y};
            float lo, hi;
            #pragma unroll
            for (int j = 0; j < 4; j++) {
                addx2(xc.x, kp[j], lo, hi);
                acc[0][j] = fmaxf(acc[0][j], fmaxf(lo, hi));   // FMNMX3 target
                addx2(xc.y, kp[j], lo, hi);
                acc[1][j] = fmaxf(acc[1][j], fmaxf(lo, hi));
            }
        }
        __syncthreads();
    }

    // ---- epilogue: two float4 stores per thread (contiguous in o) ----
    #pragma unroll
    for (int i = 0; i < 2; i++) {
        float4 r = make_float4(acc[i][0], acc[i][1], acc[i][2], acc[i][3]);
        *reinterpret_cast<float4*>(
            &out[(size_t)(b0 + tb * 2 + i) * O_DIM + o0 + to * 4]) = r;
    }
}

extern "C" void kernel_launch(void* const* d_in, const int* in_sizes, int n_in,
                              void* d_out, int out_size) {
    const float* X = (const float*)d_in[0];   // [1024, 512]
    const float* K = (const float*)d_in[1];   // [2, 512, 256]
    float* out     = (float*)d_out;           // [1024, 256]

    dim3 grid(O_DIM / BO, B_DIM / BM);        // (8, 32) = 256 blocks x 128 thr
    tropical_dense_kernel<<<grid, NTHREADS>>>(X, K, out);
}

// round 5
// speedup vs baseline: 1.0054x; 1.0054x over previous
#include <cuda_runtime.h>
#include <cstdint>

// TropicalDense: out[b,o] = max_{s,d} ( (s?-X[b,d]:X[b,d]) + K[s,d,o] )
// B=1024, D=512, O=256, float32.
//
// Two-kernel plan:
//  1) prepass: Xt[d][b]=(x,-x) transposed pre-negated; Kp[d][o]=(K0,K1) interleaved.
//  2) main:    cp.async double-buffered max-plus GEMM, raw 16B tile copies.

#define B_DIM 1024
#define D_DIM 512
#define O_DIM 256

#define BM 64
#define BO 32
#define DC 32
#define NCHUNK (D_DIM / DC)   // 16
#define NTHREADS 256

// global scratch (device globals are the sanctioned scratch mechanism)
__device__ float2 g_Xt[D_DIM * B_DIM];   // [d][b] -> (x, -x)       4 MB
__device__ float2 g_Kp[D_DIM * O_DIM];   // [d][o] -> (K0, K1)      1 MB

// ---- packed f32x2 add (fma pipe): (x+k0, -x+k1) in one instruction ----
__device__ __forceinline__ void addx2(unsigned long long a, unsigned long long b,
                                      float& lo, float& hi) {
    unsigned long long d;
    asm("add.rn.f32x2 %0, %1, %2;" : "=l"(d) : "l"(a), "l"(b));
    asm("mov.b64 {%0, %1}, %2;" : "=f"(lo), "=f"(hi) : "l"(d));
}

// ---- cp.async helpers ----
__device__ __forceinline__ void cp16(uint32_t sdst, const void* gsrc) {
    asm volatile("cp.async.ca.shared.global [%0], [%1], 16;\n"
                 :: "r"(sdst), "l"(gsrc));
}
__device__ __forceinline__ void cp_commit() {
    asm volatile("cp.async.commit_group;\n");
}
__device__ __forceinline__ void cp_wait_all() {
    asm volatile("cp.async.wait_group 0;\n" ::: "memory");
}

// ============================ prepass ============================
__global__ void prepack_kernel(const float* __restrict__ X,
                               const float* __restrict__ K) {
    int idx = blockIdx.x * blockDim.x + threadIdx.x;
    if (idx < D_DIM * B_DIM) {
        int d = idx >> 10;            // / B_DIM
        int b = idx & (B_DIM - 1);
        float v = X[(size_t)b * D_DIM + d];   // strided read, L2-resident (X=2MB)
        g_Xt[idx] = make_float2(v, -v);
    } else {
        int j = idx - D_DIM * B_DIM;
        if (j < D_DIM * O_DIM) {
            g_Kp[j] = make_float2(K[j], K[D_DIM * O_DIM + j]);  // both coalesced
        }
    }
}

// ============================ main ============================
__global__ void __launch_bounds__(NTHREADS, 1)
tropical_main_kernel(float* __restrict__ out) {
    // raw pre-transformed tiles, double buffered: 48 KB total
    __shared__ float2 Xs[2][DC][BM];   // [buf][dd][b]  (x,-x)
    __shared__ float2 Ks[2][DC][BO];   // [buf][dd][o]  (k0,k1)

    const int tid = threadIdx.x;
    const int to  = tid & 7;      // o-group: 4 cols at o0 + to*4
    const int tb  = tid >> 3;     // b-group: 2 rows at b0 + tb*2
    const int b0  = blockIdx.y * BM;
    const int o0  = blockIdx.x * BO;

    float acc[2][4];
    #pragma unroll
    for (int i = 0; i < 2; i++)
        #pragma unroll
        for (int j = 0; j < 4; j++)
            acc[i][j] = __int_as_float(0xff800000);   // -inf

    // per-chunk tile loader: raw 16B async copies, fully coalesced
    auto load_chunk = [&](int c, int buf) {
        int dg = c * DC;
        // X tile: DC x BM pairs = 1024 x 16B slots, 4 per thread
        #pragma unroll
        for (int k = 0; k < 4; k++) {
            int s  = tid + k * NTHREADS;       // 0..1023
            int dd = s >> 5;                   // 32 16B-slots per dd row
            int bp = s & 31;
            cp16((uint32_t)__cvta_generic_to_shared(&Xs[buf][dd][bp * 2]),
                 &g_Xt[(size_t)(dg + dd) * B_DIM + b0 + bp * 2]);
        }
        // K tile: DC x BO pairs = 512 x 16B slots, 2 per thread
        #pragma unroll
        for (int k = 0; k < 2; k++) {
            int s  = tid + k * NTHREADS;       // 0..511
            int dd = s >> 4;                   // 16 16B-slots per dd row
            int op = s & 15;
            cp16((uint32_t)__cvta_generic_to_shared(&Ks[buf][dd][op * 2]),
                 &g_Kp[(size_t)(dg + dd) * O_DIM + o0 + op * 2]);
        }
    };

    load_chunk(0, 0);
    cp_commit();

    for (int c = 0; c < NCHUNK; c++) {
        const int buf = c & 1;
        cp_wait_all();          // chunk c resident (waits this warp's groups)
        __syncthreads();        // visible to all warps; also fences compute(c-1)
        if (c + 1 < NCHUNK) {   // overlap next chunk's loads with compute(c)
            load_chunk(c + 1, buf ^ 1);
            cp_commit();
        }

        // ---- hot loop: per dd = 3 LDS.128 + 8 ADDX2(fma) + 16 FMNMX(alu) ----
        ulonglong2 xv = *reinterpret_cast<const ulonglong2*>(&Xs[buf][0][tb * 2]);
        ulonglong2 ka = *reinterpret_cast<const ulonglong2*>(&Ks[buf][0][to * 4]);
        ulonglong2 kb = *reinterpret_cast<const ulonglong2*>(&Ks[buf][0][to * 4 + 2]);

        #pragma unroll 8
        for (int dd = 0; dd < DC; dd++) {
            ulonglong2 xc = xv, kac = ka, kbc = kb;
            if (dd + 1 < DC) {   // register prefetch of next dd
                xv = *reinterpret_cast<const ulonglong2*>(&Xs[buf][dd + 1][tb * 2]);
                ka = *reinterpret_cast<const ulonglong2*>(&Ks[buf][dd + 1][to * 4]);
                kb = *reinterpret_cast<const ulonglong2*>(&Ks[buf][dd + 1][to * 4 + 2]);
            }
            unsigned long long kp[4] = {kac.x, kac.y, kbc.x, kbc.y};
            float lo, hi;
            #pragma unroll
            for (int j = 0; j < 4; j++) {
                addx2(xc.x, kp[j], lo, hi);
                acc[0][j] = fmaxf(acc[0][j], fmaxf(lo, hi));
                addx2(xc.y, kp[j], lo, hi);
                acc[1][j] = fmaxf(acc[1][j], fmaxf(lo, hi));
            }
        }
        // no trailing sync: next iteration's __syncthreads covers reuse safety
    }

    // ---- epilogue: 2 float4 stores per thread ----
    #pragma unroll
    for (int i = 0; i < 2; i++) {
        float4 r = make_float4(acc[i][0], acc[i][1], acc[i][2], acc[i][3]);
        *reinterpret_cast<float4*>(
            &out[(size_t)(b0 + tb * 2 + i) * O_DIM + o0 + to * 4]) = r;
    }
}

extern "C" void kernel_launch(void* const* d_in, const int* in_sizes, int n_in,
                              void* d_out, int out_size) {
    const float* X = (const float*)d_in[0];   // [1024, 512]
    const float* K = (const float*)d_in[1];   // [2, 512, 256]
    float* out     = (float*)d_out;           // [1024, 256]

    // prepass: 512*1024 + 512*256 = 655360 slots
    int total = D_DIM * B_DIM + D_DIM * O_DIM;
    prepack_kernel<<<(total + 255) / 256, 256>>>(X, K);

    dim3 grid(O_DIM / BO, B_DIM / BM);        // (8, 16) = 128 blocks, 1 wave
    tropical_main_kernel<<<grid, NTHREADS>>>(out);
}

// round 7
// speedup vs baseline: 1.7380x; 1.7287x over previous
#include <cuda_runtime.h>
#include <cstdint>

// TropicalDense: out[b,o] = max_{s,d} ( (s?-X[b,d]:X[b,d]) + K[s,d,o] )
// B=1024, D=512, O=256, float32.
// 3-kernel plan: prepack (transpose+negate X, interleave K) ->
//                main (TM=8 x TO=4 reg-tile, D-split 4, cp.async) ->
//                combine (max over 4 partials).

#define B_DIM 1024
#define D_DIM 512
#define O_DIM 256

#define BM 128
#define BO 64
#define TM 8
#define TO 4
#define DSPLIT 4
#define DPER (D_DIM / DSPLIT)   // 128
#define DC 16
#define NCHUNK (DPER / DC)      // 8
#define NTHREADS 256
#define NOUT (B_DIM * O_DIM)    // 262144

__device__ float2 g_Xt[D_DIM * B_DIM];        // [d][b] -> (x, -x)
__device__ float2 g_Kp[D_DIM * O_DIM];        // [d][o] -> (K0, K1)
__device__ float  g_part[DSPLIT * NOUT];      // partial maxima per d-split

// packed f32x2 add (fma pipe): one instr for (x+k0, -x+k1)
__device__ __forceinline__ void addx2(unsigned long long a, unsigned long long b,
                                      float& lo, float& hi) {
    unsigned long long d;
    asm("add.rn.f32x2 %0, %1, %2;" : "=l"(d) : "l"(a), "l"(b));
    asm("mov.b64 {%0, %1}, %2;" : "=f"(lo), "=f"(hi) : "l"(d));
}

__device__ __forceinline__ void cp16(uint32_t sdst, const void* gsrc) {
    asm volatile("cp.async.ca.shared.global [%0], [%1], 16;\n" :: "r"(sdst), "l"(gsrc));
}
__device__ __forceinline__ void cp_commit() { asm volatile("cp.async.commit_group;\n"); }
__device__ __forceinline__ void cp_wait_all() {
    asm volatile("cp.async.wait_group 0;\n" ::: "memory");
}

// ============================ prepass ============================
__global__ void prepack_kernel(const float* __restrict__ X,
                               const float* __restrict__ K) {
    int idx = blockIdx.x * blockDim.x + threadIdx.x;
    if (idx < D_DIM * B_DIM) {
        int d = idx >> 10;
        int b = idx & (B_DIM - 1);
        float v = X[(size_t)b * D_DIM + d];
        g_Xt[idx] = make_float2(v, -v);
    } else {
        int j = idx - D_DIM * B_DIM;
        if (j < D_DIM * O_DIM)
            g_Kp[j] = make_float2(K[j], K[D_DIM * O_DIM + j]);
    }
}

// ============================ main ============================
__global__ void __launch_bounds__(NTHREADS, 1)
tropical_main_kernel() {
    __shared__ float2 Xs[2][DC][BM];   // 32 KB
    __shared__ float2 Ks[2][DC][BO];   // 16 KB

    const int tid = threadIdx.x;
    const int to  = tid & 15;     // o-group: 4 cols at o0 + to*4
    const int tb  = tid >> 4;     // b-group: 8 rows at b0 + tb*8
    const int b0  = blockIdx.y * BM;
    const int o0  = blockIdx.x * BO;
    const int d0  = blockIdx.z * DPER;

    float acc[TM][TO];
    #pragma unroll
    for (int i = 0; i < TM; i++)
        #pragma unroll
        for (int j = 0; j < TO; j++)
            acc[i][j] = __int_as_float(0xff800000);   // -inf

    auto load_chunk = [&](int c, int buf) {
        int dbase = d0 + c * DC;
        #pragma unroll
        for (int k = 0; k < 4; k++) {                 // X: 1024 16B slots
            int s  = tid + k * NTHREADS;
            int dd = s >> 6;
            int p  = (s & 63) * 2;
            cp16((uint32_t)__cvta_generic_to_shared(&Xs[buf][dd][p]),
                 &g_Xt[(size_t)(dbase + dd) * B_DIM + b0 + p]);
        }
        #pragma unroll
        for (int k = 0; k < 2; k++) {                 // K: 512 16B slots
            int s  = tid + k * NTHREADS;
            int dd = s >> 5;
            int p  = (s & 31) * 2;
            cp16((uint32_t)__cvta_generic_to_shared(&Ks[buf][dd][p]),
                 &g_Kp[(size_t)(dbase + dd) * O_DIM + o0 + p]);
        }
    };

    load_chunk(0, 0);
    cp_commit();

    for (int c = 0; c < NCHUNK; c++) {
        const int buf = c & 1;
        cp_wait_all();
        __syncthreads();
        if (c + 1 < NCHUNK) { load_chunk(c + 1, buf ^ 1); cp_commit(); }

        // stage dd=0 (6 LDS.128)
        ulonglong2 x01 = *reinterpret_cast<const ulonglong2*>(&Xs[buf][0][tb * 8]);
        ulonglong2 x23 = *reinterpret_cast<const ulonglong2*>(&Xs[buf][0][tb * 8 + 2]);
        ulonglong2 x45 = *reinterpret_cast<const ulonglong2*>(&Xs[buf][0][tb * 8 + 4]);
        ulonglong2 x67 = *reinterpret_cast<const ulonglong2*>(&Xs[buf][0][tb * 8 + 6]);
        ulonglong2 k01 = *reinterpret_cast<const ulonglong2*>(&Ks[buf][0][to * 4]);
        ulonglong2 k23 = *reinterpret_cast<const ulonglong2*>(&Ks[buf][0][to * 4 + 2]);

        for (int dd = 0; dd < DC; dd++) {
            unsigned long long xp[TM] = {x01.x, x01.y, x23.x, x23.y,
                                         x45.x, x45.y, x67.x, x67.y};
            unsigned long long kp[TO] = {k01.x, k01.y, k23.x, k23.y};
            // register prefetch of next dd (wraps harmlessly on last iter)
            int nn = (dd + 1) & (DC - 1);
            x01 = *reinterpret_cast<const ulonglong2*>(&Xs[buf][nn][tb * 8]);
            x23 = *reinterpret_cast<const ulonglong2*>(&Xs[buf][nn][tb * 8 + 2]);
            x45 = *reinterpret_cast<const ulonglong2*>(&Xs[buf][nn][tb * 8 + 4]);
            x67 = *reinterpret_cast<const ulonglong2*>(&Xs[buf][nn][tb * 8 + 6]);
            k01 = *reinterpret_cast<const ulonglong2*>(&Ks[buf][nn][to * 4]);
            k23 = *reinterpret_cast<const ulonglong2*>(&Ks[buf][nn][to * 4 + 2]);

            #pragma unroll
            for (int i = 0; i < TM; i++)
                #pragma unroll
                for (int j = 0; j < TO; j++) {
                    float lo, hi;
                    addx2(xp[i], kp[j], lo, hi);
                    acc[i][j] = fmaxf(acc[i][j], fmaxf(lo, hi));  // max3 pattern
                }
        }
        // no trailing sync: next iteration's __syncthreads covers buffer reuse
    }

    // epilogue: 8 float4 stores into this d-split's partial plane
    float* dst = g_part + (size_t)blockIdx.z * NOUT;
    #pragma unroll
    for (int i = 0; i < TM; i++) {
        float4 r = make_float4(acc[i][0], acc[i][1], acc[i][2], acc[i][3]);
        *reinterpret_cast<float4*>(
            &dst[(size_t)(b0 + tb * 8 + i) * O_DIM + o0 + to * 4]) = r;
    }
}

// ============================ combine ============================
__global__ void combine_kernel(float* __restrict__ out) {
    int t = blockIdx.x * blockDim.x + threadIdx.x;   // 65536 threads, 4 outs each
    const float4* p = reinterpret_cast<const float4*>(g_part);
    const int N4 = NOUT / 4;
    float4 a = p[t];
    float4 b = p[t + N4];
    float4 c = p[t + 2 * N4];
    float4 d = p[t + 3 * N4];
    float4 r;
    r.x = fmaxf(fmaxf(a.x, b.x), fmaxf(c.x, d.x));
    r.y = fmaxf(fmaxf(a.y, b.y), fmaxf(c.y, d.y));
    r.z = fmaxf(fmaxf(a.z, b.z), fmaxf(c.z, d.z));
    r.w = fmaxf(fmaxf(a.w, b.w), fmaxf(c.w, d.w));
    reinterpret_cast<float4*>(out)[t] = r;
}

extern "C" void kernel_launch(void* const* d_in, const int* in_sizes, int n_in,
                              void* d_out, int out_size) {
    const float* X = (const float*)d_in[0];   // [1024, 512]
    const float* K = (const float*)d_in[1];   // [2, 512, 256]
    float* out     = (float*)d_out;           // [1024, 256]

    int total = D_DIM * B_DIM + D_DIM * O_DIM;
    prepack_kernel<<<(total + 255) / 256, 256>>>(X, K);

    dim3 grid(O_DIM / BO, B_DIM / BM, DSPLIT);   // (4, 8, 4) = 128 CTAs
    tropical_main_kernel<<<grid, NTHREADS>>>();

    combine_kernel<<<(NOUT / 4) / 256, 256>>>(out);
}

// round 8
// speedup vs baseline: 1.7417x; 1.0021x over previous
#include <cuda_runtime.h>
#include <cstdint>

// TropicalDense: out[b,o] = max_{s,d} ( (s?-X[b,d]:X[b,d]) + K[s,d,o] )
// B=1024, D=512, O=256, float32.
//
// Pipeline: prepack_x (coalesced smem transpose, pre-negated pairs)
//           prepack_k (interleave (K0,K1), +512 bias so candidates are positive)
//           main      (TM=8 x TO=4 reg tile, D-split 4, cp.async,
//                      3-input integer max on positive-float bits)
//           combine   (int max over 4 partials, de-bias)

#define B_DIM 1024
#define D_DIM 512
#define O_DIM 256

#define BM 128
#define BO 64
#define TM 8
#define TO 4
#define DSPLIT 4
#define DPER (D_DIM / DSPLIT)   // 128
#define DC 16
#define NCHUNK (DPER / DC)      // 8
#define NTHREADS 256
#define NOUT (B_DIM * O_DIM)    // 262144
#define BIAS 512.0f

__device__ float2 g_Xt[D_DIM * B_DIM];     // [d][b] -> (x, -x)
__device__ float2 g_Kp[D_DIM * O_DIM];     // [d][o] -> (K0+512, K1+512)
__device__ int    g_part[DSPLIT * NOUT];   // partial maxima (positive-float bits)

// packed f32x2 add (fma pipe): one instr for (x+k0', -x+k1')
__device__ __forceinline__ void addx2(unsigned long long a, unsigned long long b,
                                      float& lo, float& hi) {
    unsigned long long d;
    asm("add.rn.f32x2 %0, %1, %2;" : "=l"(d) : "l"(a), "l"(b));
    asm("mov.b64 {%0, %1}, %2;" : "=f"(lo), "=f"(hi) : "l"(d));
}

__device__ __forceinline__ void cp16(uint32_t sdst, const void* gsrc) {
    asm volatile("cp.async.ca.shared.global [%0], [%1], 16;\n" :: "r"(sdst), "l"(gsrc));
}
__device__ __forceinline__ void cp_commit() { asm volatile("cp.async.commit_group;\n"); }
__device__ __forceinline__ void cp_wait_all() {
    asm volatile("cp.async.wait_group 0;\n" ::: "memory");
}

// ======================= prepack X: coalesced transpose =======================
__global__ void prepack_x_kernel(const float* __restrict__ X) {
    __shared__ float s[32][33];
    const int b0 = blockIdx.x * 32;
    const int d0 = blockIdx.y * 32;
    const int tx = threadIdx.x;        // 0..31
    const int ty = threadIdx.y;        // 0..7
    #pragma unroll
    for (int k = 0; k < 4; k++) {      // coalesced reads along d
        int row = ty + k * 8;          // b within tile
        s[row][tx] = X[(size_t)(b0 + row) * D_DIM + d0 + tx];
    }
    __syncthreads();
    #pragma unroll
    for (int k = 0; k < 4; k++) {      // coalesced float2 writes along b
        int drow = ty + k * 8;         // d within tile
        float v = s[tx][drow];         // stride-33 read: conflict-free
        g_Xt[(size_t)(d0 + drow) * B_DIM + b0 + tx] = make_float2(v, -v);
    }
}

// ======================= prepack K: interleave + bias =======================
__global__ void prepack_k_kernel(const float* __restrict__ K) {
    int j = blockIdx.x * blockDim.x + threadIdx.x;   // 0 .. 131071
    g_Kp[j] = make_float2(K[j] + BIAS, K[(size_t)D_DIM * O_DIM + j] + BIAS);
}

// ============================ main ============================
__global__ void __launch_bounds__(NTHREADS, 1)
tropical_main_kernel() {
    __shared__ float2 Xs[2][DC][BM];   // 32 KB
    __shared__ float2 Ks[2][DC][BO];   // 16 KB

    const int tid = threadIdx.x;
    const int to  = tid & 15;     // o-group: 4 cols at o0 + to*4
    const int tb  = tid >> 4;     // b-group: 8 rows at b0 + tb*8
    const int b0  = blockIdx.y * BM;
    const int o0  = blockIdx.x * BO;
    const int d0  = blockIdx.z * DPER;

    // all candidates ~[500,524] -> positive-float bits monotone as s32; init 0
    int acc[TM][TO];
    #pragma unroll
    for (int i = 0; i < TM; i++)
        #pragma unroll
        for (int j = 0; j < TO; j++)
            acc[i][j] = 0;

    auto load_chunk = [&](int c, int buf) {
        int dbase = d0 + c * DC;
        #pragma unroll
        for (int k = 0; k < 4; k++) {                 // X: 1024 16B slots
            int s  = tid + k * NTHREADS;
            int dd = s >> 6;
            int p  = (s & 63) * 2;
            cp16((uint32_t)__cvta_generic_to_shared(&Xs[buf][dd][p]),
                 &g_Xt[(size_t)(dbase + dd) * B_DIM + b0 + p]);
        }
        #pragma unroll
        for (int k = 0; k < 2; k++) {                 // K: 512 16B slots
            int s  = tid + k * NTHREADS;
            int dd = s >> 5;
            int p  = (s & 31) * 2;
            cp16((uint32_t)__cvta_generic_to_shared(&Ks[buf][dd][p]),
                 &g_Kp[(size_t)(dbase + dd) * O_DIM + o0 + p]);
        }
    };

    load_chunk(0, 0);
    cp_commit();

    for (int c = 0; c < NCHUNK; c++) {
        const int buf = c & 1;
        cp_wait_all();
        __syncthreads();
        if (c + 1 < NCHUNK) { load_chunk(c + 1, buf ^ 1); cp_commit(); }

        ulonglong2 x01 = *reinterpret_cast<const ulonglong2*>(&Xs[buf][0][tb * 8]);
        ulonglong2 x23 = *reinterpret_cast<const ulonglong2*>(&Xs[buf][0][tb * 8 + 2]);
        ulonglong2 x45 = *reinterpret_cast<const ulonglong2*>(&Xs[buf][0][tb * 8 + 4]);
        ulonglong2 x67 = *reinterpret_cast<const ulonglong2*>(&Xs[buf][0][tb * 8 + 6]);
        ulonglong2 k01 = *reinterpret_cast<const ulonglong2*>(&Ks[buf][0][to * 4]);
        ulonglong2 k23 = *reinterpret_cast<const ulonglong2*>(&Ks[buf][0][to * 4 + 2]);

        for (int dd = 0; dd < DC; dd++) {
            unsigned long long xp[TM] = {x01.x, x01.y, x23.x, x23.y,
                                         x45.x, x45.y, x67.x, x67.y};
            unsigned long long kp[TO] = {k01.x, k01.y, k23.x, k23.y};
            int nn = (dd + 1) & (DC - 1);   // prefetch next dd (wrap harmless)
            x01 = *reinterpret_cast<const ulonglong2*>(&Xs[buf][nn][tb * 8]);
            x23 = *reinterpret_cast<const ulonglong2*>(&Xs[buf][nn][tb * 8 + 2]);
            x45 = *reinterpret_cast<const ulonglong2*>(&Xs[buf][nn][tb * 8 + 4]);
            x67 = *reinterpret_cast<const ulonglong2*>(&Xs[buf][nn][tb * 8 + 6]);
            k01 = *reinterpret_cast<const ulonglong2*>(&Ks[buf][nn][to * 4]);
            k23 = *reinterpret_cast<const ulonglong2*>(&Ks[buf][nn][to * 4 + 2]);

            #pragma unroll
            for (int i = 0; i < TM; i++)
                #pragma unroll
                for (int j = 0; j < TO; j++) {
                    float lo, hi;
                    addx2(xp[i], kp[j], lo, hi);
                    // one 3-input integer max replaces two FMNMX
                    acc[i][j] = __vimax3_s32(acc[i][j],
                                             __float_as_int(lo),
                                             __float_as_int(hi));
                }
        }
    }

    int* dst = g_part + (size_t)blockIdx.z * NOUT;
    #pragma unroll
    for (int i = 0; i < TM; i++) {
        int4 r = make_int4(acc[i][0], acc[i][1], acc[i][2], acc[i][3]);
        *reinterpret_cast<int4*>(
            &dst[(size_t)(b0 + tb * 8 + i) * O_DIM + o0 + to * 4]) = r;
    }
}

// ============================ combine ============================
__global__ void combine_kernel(float* __restrict__ out) {
    int t = blockIdx.x * blockDim.x + threadIdx.x;   // 65536 threads
    const int4* p = reinterpret_cast<const int4*>(g_part);
    const int N4 = NOUT / 4;
    int4 a = p[t];
    int4 b = p[t + N4];
    int4 c = p[t + 2 * N4];
    int4 d = p[t + 3 * N4];
    float4 r;
    r.x = __int_as_float(max(__vimax3_s32(a.x, b.x, c.x), d.x)) - BIAS;
    r.y = __int_as_float(max(__vimax3_s32(a.y, b.y, c.y), d.y)) - BIAS;
    r.z = __int_as_float(max(__vimax3_s32(a.z, b.z, c.z), d.z)) - BIAS;
    r.w = __int_as_float(max(__vimax3_s32(a.w, b.w, c.w), d.w)) - BIAS;
    reinterpret_cast<float4*>(out)[t] = r;
}

extern "C" void kernel_launch(void* const* d_in, const int* in_sizes, int n_in,
                              void* d_out, int out_size) {
    const float* X = (const float*)d_in[0];   // [1024, 512]
    const float* K = (const float*)d_in[1];   // [2, 512, 256]
    float* out     = (float*)d_out;           // [1024, 256]

    dim3 xgrid(B_DIM / 32, D_DIM / 32);       // (32, 16)
    prepack_x_kernel<<<xgrid, dim3(32, 8)>>>(X);
    prepack_k_kernel<<<(D_DIM * O_DIM) / 256, 256>>>(K);

    dim3 grid(O_DIM / BO, B_DIM / BM, DSPLIT);   // (4, 8, 4) = 128 CTAs
    tropical_main_kernel<<<grid, NTHREADS>>>();

    combine_kernel<<<(NOUT / 4) / 256, 256>>>(out);
}

// round 10
// speedup vs baseline: 1.7453x; 1.0021x over previous
#include <cuda_runtime.h>
#include <cstdint>

// TropicalDense: out[b,o] = max_{s,d} ( (s?-X[b,d]:X[b,d]) + K[s,d,o] )
// B=1024, D=512, O=256, float32.
//
// prepack  : X -> transposed (x,-x) pairs; K -> interleaved (K0+512, K1+512)
// main     : TM=8 x TO=4 reg tile, D-split 8 (grid 256, 2 CTAs/SM), cp.async
//            positive-bias int-max accumulate
// combine  : int max over 8 partial planes, de-bias

#define B_DIM 1024
#define D_DIM 512
#define O_DIM 256

#define BM 128
#define BO 64
#define TM 8
#define TO 4
#define DSPLIT 8
#define DPER (D_DIM / DSPLIT)   // 64
#define DC 16
#define NCHUNK (DPER / DC)      // 4
#define NTHREADS 256
#define NOUT (B_DIM * O_DIM)    // 262144
#define BIAS 512.0f

__device__ float2 g_Xt[D_DIM * B_DIM];     // [d][b] -> (x, -x)
__device__ float2 g_Kp[D_DIM * O_DIM];     // [d][o] -> (K0+512, K1+512)
__device__ int    g_part[DSPLIT * NOUT];   // partial maxima (positive-float bits)

__device__ __forceinline__ void addx2(unsigned long long a, unsigned long long b,
                                      float& lo, float& hi) {
    unsigned long long d;
    asm("add.rn.f32x2 %0, %1, %2;" : "=l"(d) : "l"(a), "l"(b));
    asm("mov.b64 {%0, %1}, %2;" : "=f"(lo), "=f"(hi) : "l"(d));
}

__device__ __forceinline__ void cp16(uint32_t sdst, const void* gsrc) {
    asm volatile("cp.async.ca.shared.global [%0], [%1], 16;\n" :: "r"(sdst), "l"(gsrc));
}
__device__ __forceinline__ void cp_commit() { asm volatile("cp.async.commit_group;\n"); }
__device__ __forceinline__ void cp_wait_all() {
    asm volatile("cp.async.wait_group 0;\n" ::: "memory");
}

// =================== fused prepack (X-transpose blocks, then K blocks) ===================
#define XBLOCKS ((B_DIM / 32) * (D_DIM / 32))   // 512

__global__ void prepack_kernel(const float* __restrict__ X,
                               const float* __restrict__ K) {
    const int bid = blockIdx.x;
    const int tid = threadIdx.x;
    if (bid < XBLOCKS) {
        __shared__ float s[32][33];
        const int b0 = (bid & 31) * 32;          // 32 b-tiles
        const int d0 = (bid >> 5) * 32;          // 16 d-tiles
        const int tx = tid & 31;
        const int ty = tid >> 5;                 // 0..7
        #pragma unroll
        for (int k = 0; k < 4; k++) {            // coalesced reads along d
            int row = ty + k * 8;
            s[row][tx] = X[(size_t)(b0 + row) * D_DIM + d0 + tx];
        }
        __syncthreads();
        #pragma unroll
        for (int k = 0; k < 4; k++) {            // coalesced float2 writes along b
            int drow = ty + k * 8;
            float v = s[tx][drow];               // stride-33: conflict-free
            g_Xt[(size_t)(d0 + drow) * B_DIM + b0 + tx] = make_float2(v, -v);
        }
    } else {
        int j = (bid - XBLOCKS) * NTHREADS + tid;            // 0 .. 131071
        g_Kp[j] = make_float2(K[j] + BIAS, K[(size_t)D_DIM * O_DIM + j] + BIAS);
    }
}

// ============================ main ============================
__global__ void __launch_bounds__(NTHREADS, 2)
tropical_main_kernel() {
    __shared__ float2 Xs[2][DC][BM];   // 32 KB
    __shared__ float2 Ks[2][DC][BO];   // 16 KB

    const int tid = threadIdx.x;
    const int to  = tid & 15;     // o-group: 4 cols at o0 + to*4
    const int tb  = tid >> 4;     // b-group: 8 rows at b0 + tb*8
    const int b0  = blockIdx.y * BM;
    const int o0  = blockIdx.x * BO;
    const int d0  = blockIdx.z * DPER;

    int acc[TM][TO];
    #pragma unroll
    for (int i = 0; i < TM; i++)
        #pragma unroll
        for (int j = 0; j < TO; j++)
            acc[i][j] = 0;           // candidates are positive-biased -> bits > 0

    auto load_chunk = [&](int c, int buf) {
        int dbase = d0 + c * DC;
        #pragma unroll
        for (int k = 0; k < 4; k++) {                 // X: 1024 16B slots
            int s  = tid + k * NTHREADS;
            int dd = s >> 6;
            int p  = (s & 63) * 2;
            cp16((uint32_t)__cvta_generic_to_shared(&Xs[buf][dd][p]),
                 &g_Xt[(size_t)(dbase + dd) * B_DIM + b0 + p]);
        }
        #pragma unroll
        for (int k = 0; k < 2; k++) {                 // K: 512 16B slots
            int s  = tid + k * NTHREADS;
            int dd = s >> 5;
            int p  = (s & 31) * 2;
            cp16((uint32_t)__cvta_generic_to_shared(&Ks[buf][dd][p]),
                 &g_Kp[(size_t)(dbase + dd) * O_DIM + o0 + p]);
        }
    };

    load_chunk(0, 0);
    cp_commit();

    for (int c = 0; c < NCHUNK; c++) {
        const int buf = c & 1;
        cp_wait_all();
        __syncthreads();
        if (c + 1 < NCHUNK) { load_chunk(c + 1, buf ^ 1); cp_commit(); }

        ulonglong2 x01 = *reinterpret_cast<const ulonglong2*>(&Xs[buf][0][tb * 8]);
        ulonglong2 x23 = *reinterpret_cast<const ulonglong2*>(&Xs[buf][0][tb * 8 + 2]);
        ulonglong2 x45 = *reinterpret_cast<const ulonglong2*>(&Xs[buf][0][tb * 8 + 4]);
        ulonglong2 x67 = *reinterpret_cast<const ulonglong2*>(&Xs[buf][0][tb * 8 + 6]);
        ulonglong2 k01 = *reinterpret_cast<const ulonglong2*>(&Ks[buf][0][to * 4]);
        ulonglong2 k23 = *reinterpret_cast<const ulonglong2*>(&Ks[buf][0][to * 4 + 2]);

        for (int dd = 0; dd < DC; dd++) {
            unsigned long long xp[TM] = {x01.x, x01.y, x23.x, x23.y,
                                         x45.x, x45.y, x67.x, x67.y};
            unsigned long long kp[TO] = {k01.x, k01.y, k23.x, k23.y};
            int nn = (dd + 1) & (DC - 1);   // prefetch next dd (wrap harmless)
            x01 = *reinterpret_cast<const ulonglong2*>(&Xs[buf][nn][tb * 8]);
            x23 = *reinterpret_cast<const ulonglong2*>(&Xs[buf][nn][tb * 8 + 2]);
            x45 = *reinterpret_cast<const ulonglong2*>(&Xs[buf][nn][tb * 8 + 4]);
            x67 = *reinterpret_cast<const ulonglong2*>(&Xs[buf][nn][tb * 8 + 6]);
            k01 = *reinterpret_cast<const ulonglong2*>(&Ks[buf][nn][to * 4]);
            k23 = *reinterpret_cast<const ulonglong2*>(&Ks[buf][nn][to * 4 + 2]);

            #pragma unroll
            for (int i = 0; i < TM; i++)
                #pragma unroll
                for (int j = 0; j < TO; j++) {
                    float lo, hi;
                    addx2(xp[i], kp[j], lo, hi);
                    acc[i][j] = __vimax3_s32(acc[i][j],
                                             __float_as_int(lo),
                                             __float_as_int(hi));
                }
        }
    }

    int* dst = g_part + (size_t)blockIdx.z * NOUT;
    #pragma unroll
    for (int i = 0; i < TM; i++) {
        int4 r = make_int4(acc[i][0], acc[i][1], acc[i][2], acc[i][3]);
        *reinterpret_cast<int4*>(
            &dst[(size_t)(b0 + tb * 8 + i) * O_DIM + o0 + to * 4]) = r;
    }
}

// ============================ combine ============================
// 128 CTAs x 256 thr; each thread reduces 2 float4-slots over 8 planes
// (16 independent int4 loads -> high MLP, latency-insensitive).
__global__ void combine_kernel(float* __restrict__ out) {
    const int base = (blockIdx.x * blockDim.x + threadIdx.x) * 2;  // slot pairs
    const int4* p = reinterpret_cast<const int4*>(g_part);
    const int N4 = NOUT / 4;                                        // 65536 slots

    int4 v[2][DSPLIT];
    #pragma unroll
    for (int u = 0; u < 2; u++)
        #pragma unroll
        for (int s = 0; s < DSPLIT; s++)
            v[u][s] = p[(size_t)s * N4 + base + u];

    #pragma unroll
    for (int u = 0; u < 2; u++) {
        int4 a = v[u][0];
        #pragma unroll
        for (int s = 1; s < DSPLIT; s++) {
            a.x = max(a.x, v[u][s].x);
            a.y = max(a.y, v[u][s].y);
            a.z = max(a.z, v[u][s].z);
            a.w = max(a.w, v[u][s].w);
        }
        float4 r;
        r.x = __int_as_float(a.x) - BIAS;
        r.y = __int_as_float(a.y) - BIAS;
        r.z = __int_as_float(a.z) - BIAS;
        r.w = __int_as_float(a.w) - BIAS;
        reinterpret_cast<float4*>(out)[base + u] = r;
    }
}

extern "C" void kernel_launch(void* const* d_in, const int* in_sizes, int n_in,
                              void* d_out, int out_size) {
    const float* X = (const float*)d_in[0];   // [1024, 512]
    const float* K = (const float*)d_in[1];   // [2, 512, 256]
    float* out     = (float*)d_out;           // [1024, 256]

    prepack_kernel<<<XBLOCKS + (D_DIM * O_DIM) / NTHREADS, NTHREADS>>>(X, K);

    dim3 grid(O_DIM / BO, B_DIM / BM, DSPLIT);   // (4, 8, 8) = 256 CTAs
    tropical_main_kernel<<<grid, NTHREADS>>>();

    combine_kernel<<<128, 256>>>(out);           // 32768 threads x 2 slots
}

// round 12
// speedup vs baseline: 1.8333x; 1.0504x over previous
#include <cuda_runtime.h>
#include <cstdint>

// TropicalDense: out[b,o] = max_{s,d} ( (s?-X[b,d]:X[b,d]) + K[s,d,o] )
// B=1024, D=512, O=256, float32.
//
// Single-pass main (no prepack kernels): each CTA prefetches raw X/K tiles
// via LDG one chunk ahead, packs (x,-x) / (k0+512,k1+512) into smem itself.
// TM=8 x TO=4 reg tile, D-split 4 (grid 128, one wave), biased int-max.
// combine: int max over 4 partial planes, de-bias.

#define B_DIM 1024
#define D_DIM 512
#define O_DIM 256

#define BM 128
#define BO 64
#define TM 8
#define TO 4
#define DSPLIT 4
#define DPER (D_DIM / DSPLIT)   // 128
#define DC 16
#define NCHUNK (DPER / DC)      // 8
#define NTHREADS 256
#define NOUT (B_DIM * O_DIM)    // 262144
#define BIAS 512.0f

__device__ int g_part[DSPLIT * NOUT];   // partial maxima (positive-float bits)

// packed f32x2 add: (x+k0, -x+k1)
__device__ __forceinline__ void addx2(unsigned long long a, unsigned long long b,
                                      float& lo, float& hi) {
    unsigned long long d;
    asm("add.rn.f32x2 %0, %1, %2;" : "=l"(d) : "l"(a), "l"(b));
    asm("mov.b64 {%0, %1}, %2;" : "=f"(lo), "=f"(hi) : "l"(d));
}

// ============================ main ============================
__global__ void __launch_bounds__(NTHREADS)
tropical_main_kernel(const float* __restrict__ X,
                     const float* __restrict__ K) {
    // single-buffer tiles (STS is post-barrier, so no double buffer needed)
    __shared__ float2 Xs[DC][BM];     // (x,-x)            16 KB
    __shared__ float2 KsA[DC][32];    // pairs o=4t,4t+1     4 KB
    __shared__ float2 KsB[DC][32];    // pairs o=4t+2,4t+3   4 KB

    const int tid = threadIdx.x;
    const int to  = tid & 15;     // o-group: 4 cols at o0 + to*4
    const int tb  = tid >> 4;     // b-group: 8 rows at b0 + tb*8
    const int b0  = blockIdx.y * BM;
    const int o0  = blockIdx.x * BO;
    const int d0  = blockIdx.z * DPER;

    // loader roles
    const int xrow = tid & 127;           // X: b row
    const int xc4  = tid >> 7;            // X: dd-group base (0/1; +2 covers 0..3)
    const int kdd  = tid >> 4;            // K: dd row 0..15
    const int ko4  = tid & 15;            // K: float4 index along o

    int acc[TM][TO];
    #pragma unroll
    for (int i = 0; i < TM; i++)
        #pragma unroll
        for (int j = 0; j < TO; j++)
            acc[i][j] = 0;               // biased candidates have positive bits

    float4 xv0, xv1, kv0, kv1;           // prefetch registers (one chunk ahead)

    auto ldg_chunk = [&](int c) {
        const int dbase = d0 + c * DC;
        const float* xb = &X[(size_t)(b0 + xrow) * D_DIM + dbase];
        xv0 = *reinterpret_cast<const float4*>(xb + xc4 * 4);
        xv1 = *reinterpret_cast<const float4*>(xb + (xc4 + 2) * 4);
        const float* kb = &K[(size_t)(dbase + kdd) * O_DIM + o0 + ko4 * 4];
        kv0 = *reinterpret_cast<const float4*>(kb);                        // K0
        kv1 = *reinterpret_cast<const float4*>(kb + (size_t)D_DIM * O_DIM); // K1
    };

    auto sts_chunk = [&]() {
        // X: 8 STS.64, conflict-free (32 consecutive rows per warp)
        Xs[xc4 * 4 + 0][xrow]       = make_float2(xv0.x, -xv0.x);
        Xs[xc4 * 4 + 1][xrow]       = make_float2(xv0.y, -xv0.y);
        Xs[xc4 * 4 + 2][xrow]       = make_float2(xv0.z, -xv0.z);
        Xs[xc4 * 4 + 3][xrow]       = make_float2(xv0.w, -xv0.w);
        Xs[(xc4 + 2) * 4 + 0][xrow] = make_float2(xv1.x, -xv1.x);
        Xs[(xc4 + 2) * 4 + 1][xrow] = make_float2(xv1.y, -xv1.y);
        Xs[(xc4 + 2) * 4 + 2][xrow] = make_float2(xv1.z, -xv1.z);
        Xs[(xc4 + 2) * 4 + 3][xrow] = make_float2(xv1.w, -xv1.w);
        // K: interleave + bias; A holds o=4t,4t+1, B holds o=4t+2,4t+3
        KsA[kdd][2 * ko4 + 0] = make_float2(kv0.x + BIAS, kv1.x + BIAS);
        KsA[kdd][2 * ko4 + 1] = make_float2(kv0.y + BIAS, kv1.y + BIAS);
        KsB[kdd][2 * ko4 + 0] = make_float2(kv0.z + BIAS, kv1.z + BIAS);
        KsB[kdd][2 * ko4 + 1] = make_float2(kv0.w + BIAS, kv1.w + BIAS);
    };

    ldg_chunk(0);

    for (int c = 0; c < NCHUNK; c++) {
        __syncthreads();                  // prior chunk's compute fully done
        sts_chunk();                      // commit prefetched regs to smem
        if (c + 1 < NCHUNK) ldg_chunk(c + 1);   // issue next chunk's LDGs now
        __syncthreads();                  // tiles visible

        // register prefetch chain over dd
        ulonglong2 x01 = *reinterpret_cast<const ulonglong2*>(&Xs[0][tb * 8]);
        ulonglong2 x23 = *reinterpret_cast<const ulonglong2*>(&Xs[0][tb * 8 + 2]);
        ulonglong2 x45 = *reinterpret_cast<const ulonglong2*>(&Xs[0][tb * 8 + 4]);
        ulonglong2 x67 = *reinterpret_cast<const ulonglong2*>(&Xs[0][tb * 8 + 6]);
        ulonglong2 k01 = *reinterpret_cast<const ulonglong2*>(&KsA[0][2 * to]);
        ulonglong2 k23 = *reinterpret_cast<const ulonglong2*>(&KsB[0][2 * to]);

        for (int dd = 0; dd < DC; dd++) {
            unsigned long long xp[TM] = {x01.x, x01.y, x23.x, x23.y,
                                         x45.x, x45.y, x67.x, x67.y};
            unsigned long long kp[TO] = {k01.x, k01.y, k23.x, k23.y};
            int nn = (dd + 1) & (DC - 1);       // wrap harmless on last iter
            x01 = *reinterpret_cast<const ulonglong2*>(&Xs[nn][tb * 8]);
            x23 = *reinterpret_cast<const ulonglong2*>(&Xs[nn][tb * 8 + 2]);
            x45 = *reinterpret_cast<const ulonglong2*>(&Xs[nn][tb * 8 + 4]);
            x67 = *reinterpret_cast<const ulonglong2*>(&Xs[nn][tb * 8 + 6]);
            k01 = *reinterpret_cast<const ulonglong2*>(&KsA[nn][2 * to]);
            k23 = *reinterpret_cast<const ulonglong2*>(&KsB[nn][2 * to]);

            #pragma unroll
            for (int i = 0; i < TM; i++)
                #pragma unroll
                for (int j = 0; j < TO; j++) {
                    float lo, hi;
                    addx2(xp[i], kp[j], lo, hi);
                    acc[i][j] = __vimax3_s32(acc[i][j],
                                             __float_as_int(lo),
                                             __float_as_int(hi));
                }
        }
    }

    int* dst = g_part + (size_t)blockIdx.z * NOUT;
    #pragma unroll
    for (int i = 0; i < TM; i++) {
        int4 r = make_int4(acc[i][0], acc[i][1], acc[i][2], acc[i][3]);
        *reinterpret_cast<int4*>(
            &dst[(size_t)(b0 + tb * 8 + i) * O_DIM + o0 + to * 4]) = r;
    }
}

// ============================ combine ============================
// 128 CTAs x 256 thr; each thread reduces 2 int4-slots over 4 planes (MLP=8)
__global__ void combine_kernel(float* __restrict__ out) {
    const int base = (blockIdx.x * blockDim.x + threadIdx.x) * 2;
    const int4* p = reinterpret_cast<const int4*>(g_part);
    const int N4 = NOUT / 4;                       // 65536 slots

    int4 v[2][DSPLIT];
    #pragma unroll
    for (int u = 0; u < 2; u++)
        #pragma unroll
        for (int s = 0; s < DSPLIT; s++)
            v[u][s] = p[(size_t)s * N4 + base + u];

    #pragma unroll
    for (int u = 0; u < 2; u++) {
        int4 a = v[u][0];
        #pragma unroll
        for (int s = 1; s < DSPLIT; s++) {
            a.x = max(a.x, v[u][s].x);
            a.y = max(a.y, v[u][s].y);
            a.z = max(a.z, v[u][s].z);
            a.w = max(a.w, v[u][s].w);
        }
        float4 r;
        r.x = __int_as_float(a.x) - BIAS;
        r.y = __int_as_float(a.y) - BIAS;
        r.z = __int_as_float(a.z) - BIAS;
        r.w = __int_as_float(a.w) - BIAS;
        reinterpret_cast<float4*>(out)[base + u] = r;
    }
}

extern "C" void kernel_launch(void* const* d_in, const int* in_sizes, int n_in,
                              void* d_out, int out_size) {
    const float* X = (const float*)d_in[0];   // [1024, 512]
    const float* K = (const float*)d_in[1];   // [2, 512, 256]
    float* out     = (float*)d_out;           // [1024, 256]

    dim3 grid(O_DIM / BO, B_DIM / BM, DSPLIT);   // (4, 8, 4) = 128 CTAs, 1 wave
    tropical_main_kernel<<<grid, NTHREADS>>>(X, K);

    combine_kernel<<<128, 256>>>(out);           // 32768 threads x 2 slots
}

// round 13
// speedup vs baseline: 1.9647x; 1.0717x over previous
#include <cuda_runtime.h>
#include <cstdint>

// TropicalDense: out[b,o] = max_{s,d} ( (s?-X[b,d]:X[b,d]) + K[s,d,o] )
// B=1024, D=512, O=256, float32.
//
// Identity: max(x+K0, -x+K1) = |x + t| + c,  t=(K0-K1)/2, c=(K0+K1)/2.
// Folds the sign axis into a free |.| operand modifier: 3 ops per 2 candidates.
// main   : TM=8 x TO=4 tile, D-split 4 (grid 128, one wave), LDG-prefetch
//          single-buffer smem, loader computes (t,c).
// combine: float max over 4 partial planes.

#define B_DIM 1024
#define D_DIM 512
#define O_DIM 256

#define BM 128
#define BO 64
#define TM 8
#define TO 4
#define DSPLIT 4
#define DPER (D_DIM / DSPLIT)   // 128
#define DC 16
#define NCHUNK (DPER / DC)      // 8
#define NTHREADS 256
#define NOUT (B_DIM * O_DIM)    // 262144

__device__ float g_part[DSPLIT * NOUT];   // partial maxima per d-split plane

// packed f32x2 add
__device__ __forceinline__ unsigned long long addx2p(unsigned long long a,
                                                     unsigned long long b) {
    unsigned long long d;
    asm("add.rn.f32x2 %0, %1, %2;" : "=l"(d) : "l"(a), "l"(b));
    return d;
}
__device__ __forceinline__ unsigned long long pack2(float lo, float hi) {
    unsigned long long d;
    asm("mov.b64 %0, {%1, %2};" : "=l"(d) : "f"(lo), "f"(hi));
    return d;
}
__device__ __forceinline__ void unpack2(unsigned long long a, float& lo, float& hi) {
    asm("mov.b64 {%0, %1}, %2;" : "=f"(lo), "=f"(hi) : "l"(a));
}

// ============================ main ============================
__global__ void __launch_bounds__(NTHREADS)
tropical_main_kernel(const float* __restrict__ X,
                     const float* __restrict__ K) {
    __shared__ float  Xs[DC][BM];     // x scalars          8 KB
    __shared__ float2 Ks[DC][BO];     // (t, c) per o       8 KB

    const int tid = threadIdx.x;
    const int to  = tid & 15;     // o-group: 4 cols at o0 + to*4
    const int tb  = tid >> 4;     // b-group: 8 rows at b0 + tb*8
    const int b0  = blockIdx.y * BM;
    const int o0  = blockIdx.x * BO;
    const int d0  = blockIdx.z * DPER;

    // loader roles
    const int xrow = tid & 127;          // X: b row (2 slots: c4 and c4+2)
    const int xc4  = tid >> 7;           // 0/1
    const int kdd  = tid >> 4;           // K: dd row 0..15
    const int ko4  = tid & 15;           // K: float4 index along o

    float acc[TM][TO];
    #pragma unroll
    for (int i = 0; i < TM; i++)
        #pragma unroll
        for (int j = 0; j < TO; j++)
            acc[i][j] = __int_as_float(0xff800000);   // -inf

    float4 xv0, xv1, kv0, kv1;           // LDG prefetch (one chunk ahead)

    auto ldg_chunk = [&](int c) {
        const int dbase = d0 + c * DC;
        const float* xb = &X[(size_t)(b0 + xrow) * D_DIM + dbase];
        xv0 = *reinterpret_cast<const float4*>(xb + xc4 * 4);
        xv1 = *reinterpret_cast<const float4*>(xb + (xc4 + 2) * 4);
        const float* kb = &K[(size_t)(dbase + kdd) * O_DIM + o0 + ko4 * 4];
        kv0 = *reinterpret_cast<const float4*>(kb);                         // K0
        kv1 = *reinterpret_cast<const float4*>(kb + (size_t)D_DIM * O_DIM); // K1
    };

    auto sts_chunk = [&]() {
        Xs[xc4 * 4 + 0][xrow]       = xv0.x;
        Xs[xc4 * 4 + 1][xrow]       = xv0.y;
        Xs[xc4 * 4 + 2][xrow]       = xv0.z;
        Xs[xc4 * 4 + 3][xrow]       = xv0.w;
        Xs[(xc4 + 2) * 4 + 0][xrow] = xv1.x;
        Xs[(xc4 + 2) * 4 + 1][xrow] = xv1.y;
        Xs[(xc4 + 2) * 4 + 2][xrow] = xv1.z;
        Xs[(xc4 + 2) * 4 + 3][xrow] = xv1.w;
        // (t, c) transform done once here, off the hot loop
        Ks[kdd][ko4 * 4 + 0] = make_float2((kv0.x - kv1.x) * 0.5f, (kv0.x + kv1.x) * 0.5f);
        Ks[kdd][ko4 * 4 + 1] = make_float2((kv0.y - kv1.y) * 0.5f, (kv0.y + kv1.y) * 0.5f);
        Ks[kdd][ko4 * 4 + 2] = make_float2((kv0.z - kv1.z) * 0.5f, (kv0.z + kv1.z) * 0.5f);
        Ks[kdd][ko4 * 4 + 3] = make_float2((kv0.w - kv1.w) * 0.5f, (kv0.w + kv1.w) * 0.5f);
    };

    ldg_chunk(0);

    for (int c = 0; c < NCHUNK; c++) {
        __syncthreads();                        // prior chunk compute done
        sts_chunk();
        if (c + 1 < NCHUNK) ldg_chunk(c + 1);   // overlap next LDGs
        __syncthreads();                        // tiles visible

        // register prefetch chain over dd
        ulonglong2 xa = *reinterpret_cast<const ulonglong2*>(&Xs[0][tb * 8]);     // x0..x3
        ulonglong2 xb = *reinterpret_cast<const ulonglong2*>(&Xs[0][tb * 8 + 4]); // x4..x7
        ulonglong2 ka = *reinterpret_cast<const ulonglong2*>(&Ks[0][to * 4]);     // (t,c)0,1
        ulonglong2 kb = *reinterpret_cast<const ulonglong2*>(&Ks[0][to * 4 + 2]); // (t,c)2,3

        for (int dd = 0; dd < DC; dd++) {
            unsigned long long xp[4] = {xa.x, xa.y, xb.x, xb.y};   // 4 b-pairs
            unsigned long long kp[4] = {ka.x, ka.y, kb.x, kb.y};   // 4 (t,c)
            int nn = (dd + 1) & (DC - 1);       // wrap harmless on last iter
            xa = *reinterpret_cast<const ulonglong2*>(&Xs[nn][tb * 8]);
            xb = *reinterpret_cast<const ulonglong2*>(&Xs[nn][tb * 8 + 4]);
            ka = *reinterpret_cast<const ulonglong2*>(&Ks[nn][to * 4]);
            kb = *reinterpret_cast<const ulonglong2*>(&Ks[nn][to * 4 + 2]);

            #pragma unroll
            for (int j = 0; j < TO; j++) {
                float t, cc;
                unpack2(kp[j], t, cc);
                unsigned long long tp = pack2(t, t);
                #pragma unroll
                for (int i2 = 0; i2 < 4; i2++) {
                    unsigned long long u = addx2p(xp[i2], tp);  // (x2i+t, x2i+1+t)
                    float ulo, uhi;
                    unpack2(u, ulo, uhi);
                    // |u| is a free operand modifier on FADD
                    acc[2 * i2 + 0][j] = fmaxf(acc[2 * i2 + 0][j], fabsf(ulo) + cc);
                    acc[2 * i2 + 1][j] = fmaxf(acc[2 * i2 + 1][j], fabsf(uhi) + cc);
                }
            }
        }
    }

    float* dst = g_part + (size_t)blockIdx.z * NOUT;
    #pragma unroll
    for (int i = 0; i < TM; i++) {
        float4 r = make_float4(acc[i][0], acc[i][1], acc[i][2], acc[i][3]);
        *reinterpret_cast<float4*>(
            &dst[(size_t)(b0 + tb * 8 + i) * O_DIM + o0 + to * 4]) = r;
    }
}

// ============================ combine ============================
// 256 CTAs x 256 thr, 1 float4-slot per thread (4 independent plane loads)
__global__ void combine_kernel(float* __restrict__ out) {
    const int t = blockIdx.x * blockDim.x + threadIdx.x;   // 0..65535 slots
    const float4* p = reinterpret_cast<const float4*>(g_part);
    const int N4 = NOUT / 4;

    float4 a = p[t];
    float4 b = p[t + N4];
    float4 c = p[t + 2 * N4];
    float4 d = p[t + 3 * N4];
    float4 r;
    r.x = fmaxf(fmaxf(a.x, b.x), fmaxf(c.x, d.x));
    r.y = fmaxf(fmaxf(a.y, b.y), fmaxf(c.y, d.y));
    r.z = fmaxf(fmaxf(a.z, b.z), fmaxf(c.z, d.z));
    r.w = fmaxf(fmaxf(a.w, b.w), fmaxf(c.w, d.w));
    reinterpret_cast<float4*>(out)[t] = r;
}

extern "C" void kernel_launch(void* const* d_in, const int* in_sizes, int n_in,
                              void* d_out, int out_size) {
    const float* X = (const float*)d_in[0];   // [1024, 512]
    const float* K = (const float*)d_in[1];   // [2, 512, 256]
    float* out     = (float*)d_out;           // [1024, 256]

    dim3 grid(O_DIM / BO, B_DIM / BM, DSPLIT);   // (4, 8, 4) = 128 CTAs, 1 wave
    tropical_main_kernel<<<grid, NTHREADS>>>(X, K);

    combine_kernel<<<256, 256>>>(out);           // 65536 threads x 1 slot
}